// round 9
// baseline (speedup 1.0000x reference)
#include <cuda_runtime.h>

// B, N, D, L = 32, 1000, 256, 3
#define BB 32
#define NN 1000
#define DD 256
#define LL 3
#define CHUNKS 50
#define ROWS_PER_CHUNK 20          // 50 * 20 = 1000
#define TOTAL4 (BB * NN * DD / 4)  // 2,048,000 float4 per output half
#define NRED (BB * CHUNKS)         // 1600 reduce CTAs
#define NCOPY 1000                 // 1000 copy CTAs * 256 thr * 8 f4 = TOTAL4

// Scratch (no device allocation allowed -> __device__ globals)
__device__ float g_partial[NRED * DD];
__device__ float g_v[BB * DD];

// ---------------------------------------------------------------------------
// K1': heterogeneous launch — reduce CTAs overlap with copy-half CTAs.
//   id < 1600 : partial mean over 20 rows (R8 shape, measured 8.6us alone)
//   id >= 1600: out[TOTAL4:] = nf   (8 front-batched loads, 8 stcs stores)
// No inter-CTA dependencies whatsoever.
// ---------------------------------------------------------------------------
__global__ __launch_bounds__(256)
void k_reduce_copy(const float* __restrict__ nf, float* __restrict__ out) {
    const int id = blockIdx.x;
    const int tid = threadIdx.x;              // 0..255
    const float4* __restrict__ nf4 = reinterpret_cast<const float4*>(nf);

    if (id < NRED) {
        // ---------------- reduce CTA ----------------
        const int x = tid & 63;               // float4 column
        const int y = tid >> 6;               // row group 0..3
        const int b = id / CHUNKS;
        const int c = id % CHUNKS;
        const int base = (b * NN + c * ROWS_PER_CHUNK) * 64;

        const float4 a0 = nf4[base + (y +  0) * 64 + x];
        const float4 a1 = nf4[base + (y +  4) * 64 + x];
        const float4 a2 = nf4[base + (y +  8) * 64 + x];
        const float4 a3 = nf4[base + (y + 12) * 64 + x];
        const float4 a4 = nf4[base + (y + 16) * 64 + x];

        float4 s;
        s.x = (a0.x + a1.x) + (a2.x + a3.x) + a4.x;
        s.y = (a0.y + a1.y) + (a2.y + a3.y) + a4.y;
        s.z = (a0.z + a1.z) + (a2.z + a3.z) + a4.z;
        s.w = (a0.w + a1.w) + (a2.w + a3.w) + a4.w;

        __shared__ float4 sm[4][64];
        sm[y][x] = s;
        __syncthreads();
        if (y == 0) {
            float4 t = sm[0][x];
            const float4 t1 = sm[1][x], t2 = sm[2][x], t3 = sm[3][x];
            t.x += t1.x + t2.x + t3.x;
            t.y += t1.y + t2.y + t3.y;
            t.z += t1.z + t2.z + t3.z;
            t.w += t1.w + t2.w + t3.w;
            reinterpret_cast<float4*>(g_partial)[id * 64 + x] = t;
        }
    } else {
        // ---------------- copy CTA: out[TOTAL4:] = nf ----------------
        float4* o4 = reinterpret_cast<float4*>(out);
        const int cid = id - NRED;            // 0..999
        const int base = cid * 2048;          // 256 thr * 8 f4

        float4 a[8];
#pragma unroll
        for (int k = 0; k < 8; k++)
            a[k] = nf4[base + k * 256 + tid];
#pragma unroll
        for (int k = 0; k < 8; k++)
            __stcs(o4 + TOTAL4 + base + k * 256 + tid, a[k]);
    }
}

// ---------------------------------------------------------------------------
// K2: finish the mean, then 3 fused 256x256 GEMVs (+bias, ReLU between).
// One CTA per batch, 1024 threads: out-column o = t&255, K-group g = t>>8.
// (The ONLY GEMV shape that is fast — see R7 post-mortem.)
// ---------------------------------------------------------------------------
__global__ void k_gcn_head(const float* __restrict__ Ws, const float* __restrict__ bs) {
    const int b = blockIdx.x;
    const int t = threadIdx.x;
    const int o = t & (DD - 1);
    const int g = t >> 8;       // 0..3

    __shared__ float sv[DD];
    __shared__ float part[4][DD];

    float s = 0.f;
#pragma unroll
    for (int c = g; c < CHUNKS; c += 4)
        s += g_partial[(b * CHUNKS + c) * DD + o];
    part[g][o] = s;
    __syncthreads();
    if (g == 0)
        sv[o] = (part[0][o] + part[1][o] + part[2][o] + part[3][o]) * (1.0f / (float)NN);
    __syncthreads();

#pragma unroll
    for (int l = 0; l < LL; l++) {
        const float* __restrict__ W = Ws + l * DD * DD;
        float acc = 0.f;
        const int k0 = g * 64;
#pragma unroll 8
        for (int k = k0; k < k0 + 64; k++)
            acc = fmaf(sv[k], W[k * DD + o], acc);   // coalesced, L2-resident
        part[g][o] = acc;
        __syncthreads();
        if (g == 0) {
            float r = part[0][o] + part[1][o] + part[2][o] + part[3][o] + bs[l * DD + o];
            sv[o] = (l < LL - 1) ? fmaxf(r, 0.f) : r;
        }
        __syncthreads();
    }
    if (g == 0) g_v[b * DD + o] = sv[o];
}

// ---------------------------------------------------------------------------
// K3': add half only: out[0:TOTAL4] = nf + v[b,:].
// 1000 CTAs * 256 thr * 8 f4 — 8 front-batched loads, 8 deep-pipelined stores.
// nf reads should be L2-hot after K1'.
// ---------------------------------------------------------------------------
__global__ __launch_bounds__(256)
void k_add(const float* __restrict__ nf, float* __restrict__ out) {
    const int tid = threadIdx.x;
    const int base = blockIdx.x * 2048;

    const float4* __restrict__ nf4 = reinterpret_cast<const float4*>(nf);
    float4* o4 = reinterpret_cast<float4*>(out);

    float4 a[8];
#pragma unroll
    for (int k = 0; k < 8; k++)
        a[k] = nf4[base + k * 256 + tid];

#pragma unroll
    for (int k = 0; k < 8; k++) {
        const int idx = base + k * 256 + tid;
        const int bb = (idx >> 6) / NN;                    // batch = row/NN, row = idx/64
        const float4 v = *reinterpret_cast<const float4*>(g_v + bb * DD + ((idx & 63) << 2));
        float4 r;
        r.x = a[k].x + v.x;
        r.y = a[k].y + v.y;
        r.z = a[k].z + v.z;
        r.w = a[k].w + v.w;
        __stcs(o4 + idx, r);
    }
}

extern "C" void kernel_launch(void* const* d_in, const int* in_sizes, int n_in,
                              void* d_out, int out_size) {
    // Inputs in metadata order: x (unused), node_feature, Ws, bs
    const float* nf = (const float*)d_in[1];
    const float* Ws = (const float*)d_in[2];
    const float* bs = (const float*)d_in[3];
    float* out = (float*)d_out;

    k_reduce_copy<<<NRED + NCOPY, 256>>>(nf, out);   // 2600 CTAs, overlapped R+W
    k_gcn_head<<<BB, 1024>>>(Ws, bs);
    k_add<<<NCOPY, 256>>>(nf, out);                  // 1000 CTAs
}

// round 11
// speedup vs baseline: 1.4995x; 1.4995x over previous
#include <cuda_runtime.h>

// B, N, D, L = 32, 1000, 256, 3
#define BB 32
#define NN 1000
#define DD 256
#define LL 3
#define CHUNKS 8
#define ROWS_PER_CHUNK 125         // 8 * 125 = 1000
#define TOTAL4 (BB * NN * DD / 4)  // 2,048,000 float4 per output half

// Scratch (no device allocation allowed -> __device__ globals)
__device__ float    g_partial[BB * CHUNKS * DD];
__device__ float    g_v[BB * DD];
__device__ unsigned g_cnt[BB];     // monotonic; (old % CHUNKS)==CHUNKS-1 -> last

// ---------------------------------------------------------------------------
// K1: fused reduce + GEMV tail.
// grid (32, 8) = 256 CTAs, block (64,16) = 1024 threads.
// Each CTA reduces 125 rows (8 front-batched LDG.128 per thread, last guarded).
// The LAST CTA to finish each batch runs the 3-layer GEMV in the champion
// 1024-thread / K-split-4 shape (the only shape measured fast; R7 post-mortem).
// ---------------------------------------------------------------------------
__global__ __launch_bounds__(1024, 1)
void k_reduce_gemv(const float* __restrict__ nf,
                   const float* __restrict__ Ws,
                   const float* __restrict__ bs) {
    const int b = blockIdx.x;      // 0..31
    const int c = blockIdx.y;      // 0..7
    const int x = threadIdx.x;     // 0..63  (float4 column)
    const int y = threadIdx.y;     // 0..15  (row group)
    const int tid = y * 64 + x;    // 0..1023

    const float4* __restrict__ nf4 = reinterpret_cast<const float4*>(nf);
    const float4 z4 = make_float4(0.f, 0.f, 0.f, 0.f);

    // -------- reduce 125 rows: r = y + 16*i, i = 0..7, guard r < 125 --------
    {
        const float4* __restrict__ p = nf4 + (size_t)(b * NN + c * ROWS_PER_CHUNK) * 64;

        float4 a[8];
#pragma unroll
        for (int i = 0; i < 8; i++) {
            const int r = y + 16 * i;
            a[i] = (r < ROWS_PER_CHUNK) ? p[r * 64 + x] : z4;
        }
        float4 s0 = z4, s1 = z4;
#pragma unroll
        for (int i = 0; i < 8; i += 2) {
            s0.x += a[i].x;   s0.y += a[i].y;   s0.z += a[i].z;   s0.w += a[i].w;
            s1.x += a[i+1].x; s1.y += a[i+1].y; s1.z += a[i+1].z; s1.w += a[i+1].w;
        }
        float4 s = make_float4(s0.x + s1.x, s0.y + s1.y, s0.z + s1.z, s0.w + s1.w);

        __shared__ float4 red[16][64];
        red[y][x] = s;
        __syncthreads();
        if (y < 8) {
            float4 t = red[y][x], u = red[y + 8][x];
            t.x += u.x; t.y += u.y; t.z += u.z; t.w += u.w;
            red[y][x] = t;
        }
        __syncthreads();
        if (y < 4) {
            float4 t = red[y][x], u = red[y + 4][x];
            t.x += u.x; t.y += u.y; t.z += u.z; t.w += u.w;
            red[y][x] = t;
        }
        __syncthreads();
        if (y == 0) {
            float4 t = red[0][x];
            const float4 t1 = red[1][x], t2 = red[2][x], t3 = red[3][x];
            t.x += t1.x + t2.x + t3.x;
            t.y += t1.y + t2.y + t3.y;
            t.z += t1.z + t2.z + t3.z;
            t.w += t1.w + t2.w + t3.w;
            reinterpret_cast<float4*>(g_partial)[(b * CHUNKS + c) * 64 + x] = t;
        }
    }

    // -------- last-CTA election (monotonic counter, replay-safe) -----------
    __shared__ unsigned s_last;
    __threadfence();                       // release the partial write
    if (tid == 0) {
        const unsigned old = atomicAdd(&g_cnt[b], 1u);
        s_last = ((old % CHUNKS) == CHUNKS - 1) ? 1u : 0u;
    }
    __syncthreads();
    if (!s_last) return;
    __threadfence();                       // acquire all partials of batch b

    // -------- GEMV tail: champion K2 shape (K-split 4) ---------------------
    __shared__ float sv[DD];
    __shared__ float part[4][DD];

    const int o = tid & (DD - 1);
    const int g = tid >> 8;                // 0..3

    // finish mean: 8 chunks strided over the 4 groups (2 each)
    {
        float s = g_partial[(b * CHUNKS + g) * DD + o]
                + g_partial[(b * CHUNKS + g + 4) * DD + o];
        part[g][o] = s;
    }
    __syncthreads();
    if (g == 0)
        sv[o] = (part[0][o] + part[1][o] + part[2][o] + part[3][o]) * (1.0f / (float)NN);
    __syncthreads();

#pragma unroll
    for (int l = 0; l < LL; l++) {
        const float* __restrict__ W = Ws + l * DD * DD;
        float acc = 0.f;
        const int k0 = g * 64;
#pragma unroll 8
        for (int k = k0; k < k0 + 64; k++)
            acc = fmaf(sv[k], W[k * DD + o], acc);   // coalesced, L2-resident
        part[g][o] = acc;
        __syncthreads();
        if (g == 0) {
            float r = part[0][o] + part[1][o] + part[2][o] + part[3][o] + bs[l * DD + o];
            sv[o] = (l < LL - 1) ? fmaxf(r, 0.f) : r;
        }
        __syncthreads();
    }
    if (g == 0) g_v[b * DD + o] = sv[o];
}

// ---------------------------------------------------------------------------
// K3: champion write kernel, verbatim.
// out[0:BND] = nf + v[b,:] ; out[BND:2BND] = nf.
// ---------------------------------------------------------------------------
__global__ void k_out(const float* __restrict__ nf, float* __restrict__ out) {
    const int stride = gridDim.x * blockDim.x;           // 512,000
    const int i0 = blockIdx.x * blockDim.x + threadIdx.x;

    const float4* __restrict__ nf4 = reinterpret_cast<const float4*>(nf);
    float4* o4 = reinterpret_cast<float4*>(out);

    const int ia = i0, ib = i0 + stride, ic = i0 + 2 * stride, id = i0 + 3 * stride;

    const float4 a0 = nf4[ia];
    const float4 a1 = nf4[ib];
    const float4 a2 = nf4[ic];
    const float4 a3 = nf4[id];

#define DO_ONE(idx, a)                                                        \
    {                                                                         \
        const int i = (idx) << 2;                                             \
        const int bb = i / (NN * DD);                                         \
        const int dd = i & (DD - 1);                                          \
        const float4 v = *reinterpret_cast<const float4*>(g_v + bb * DD + dd);\
        float4 r;                                                             \
        r.x = (a).x + v.x; r.y = (a).y + v.y;                                 \
        r.z = (a).z + v.z; r.w = (a).w + v.w;                                 \
        __stcs(o4 + (idx), r);                                                \
        __stcs(o4 + TOTAL4 + (idx), (a));                                     \
    }

    DO_ONE(ia, a0)
    DO_ONE(ib, a1)
    DO_ONE(ic, a2)
    DO_ONE(id, a3)
#undef DO_ONE
}

extern "C" void kernel_launch(void* const* d_in, const int* in_sizes, int n_in,
                              void* d_out, int out_size) {
    // Inputs in metadata order: x (unused), node_feature, Ws, bs
    const float* nf = (const float*)d_in[1];
    const float* Ws = (const float*)d_in[2];
    const float* bs = (const float*)d_in[3];
    float* out = (float*)d_out;

    dim3 g1(BB, CHUNKS);       // 256 CTAs
    dim3 b1(64, 16);           // 1024 threads
    k_reduce_gemv<<<g1, b1>>>(nf, Ws, bs);

    // 2000 blocks * 256 threads * 4 float4/thread = 2,048,000 = TOTAL4 exactly
    k_out<<<2000, 256>>>(nf, out);
}